// round 15
// baseline (speedup 1.0000x reference)
#include <cuda_runtime.h>
#include <cuda_fp16.h>
#include <cstdint>

// ---------------------------------------------------------------------------
// Problem constants
// ---------------------------------------------------------------------------
#define EDIM   1024
#define NAQ    128
#define BSZ    256
#define NROWS  (BSZ * NAQ)          // 32768
#define QKVDIM 3072
#define HEADS  16
#define HDIM   64
#define NBH    (BSZ * HEADS)        // 4096 attention batches
#define OUT_ELEMS (NROWS * EDIM)
#define NTILES 3072                 // 256 bm x 12 bn
#define NSM    148

// ---------------------------------------------------------------------------
// Scratch (device globals: allocation-free)
// ---------------------------------------------------------------------------
__device__ float g_xn  [(size_t)NROWS * EDIM];       // ln1(x), tf32-rounded
__device__ float g_qkv [(size_t)NROWS * QKVDIM];     // qkv (q scaled), tf32-rounded
__device__ float g_attn[(size_t)NROWS * EDIM];       // attention output
__device__ float g_wtf [(size_t)QKVDIM * EDIM];      // in_w, fragment-permuted tf32

// ---------------------------------------------------------------------------
// Helpers (portable subset: harness lowers through compute_103)
// ---------------------------------------------------------------------------
__device__ __forceinline__ uint32_t smem_u32(const void* p) {
    uint32_t a;
    asm("{ .reg .u64 t; cvta.to.shared.u64 t, %1; cvt.u32.u64 %0, t; }"
        : "=r"(a) : "l"(p));
    return a;
}
__device__ __forceinline__ void cp_async16(uint32_t dst, const void* src) {
    asm volatile("cp.async.cg.shared.global [%0], [%1], 16;"
                 :: "r"(dst), "l"(src) : "memory");
}
#define CP_COMMIT() asm volatile("cp.async.commit_group;" ::: "memory")

__device__ __forceinline__ uint32_t f2tf(float f) {
    uint32_t r;
    asm("cvt.rna.tf32.f32 %0, %1;" : "=r"(r) : "f"(f));
    return r;
}
__device__ __forceinline__ float roundtf(float f) {
    return __uint_as_float(f2tf(f));
}
__device__ __forceinline__ void mma_tf32(float* c, const uint32_t* a,
                                         uint32_t b0, uint32_t b1) {
    asm volatile(
        "mma.sync.aligned.m16n8k8.row.col.f32.tf32.tf32.f32 "
        "{%0,%1,%2,%3}, {%4,%5,%6,%7}, {%8,%9}, {%0,%1,%2,%3};"
        : "+f"(c[0]), "+f"(c[1]), "+f"(c[2]), "+f"(c[3])
        : "r"(a[0]), "r"(a[1]), "r"(a[2]), "r"(a[3]), "r"(b0), "r"(b1));
}
__device__ __forceinline__ void mma_f16(float* c, const uint32_t* a,
                                        uint32_t b0, uint32_t b1) {
    asm volatile(
        "mma.sync.aligned.m16n8k16.row.col.f32.f16.f16.f32 "
        "{%0,%1,%2,%3}, {%4,%5,%6,%7}, {%8,%9}, {%0,%1,%2,%3};"
        : "+f"(c[0]), "+f"(c[1]), "+f"(c[2]), "+f"(c[3])
        : "r"(a[0]), "r"(a[1]), "r"(a[2]), "r"(a[3]), "r"(b0), "r"(b1));
}
__device__ __forceinline__ void ldsm4(uint32_t* r, uint32_t addr) {
    asm volatile("ldmatrix.sync.aligned.m8n8.x4.shared.b16 {%0,%1,%2,%3}, [%4];"
                 : "=r"(r[0]), "=r"(r[1]), "=r"(r[2]), "=r"(r[3]) : "r"(addr));
}

// ---------------------------------------------------------------------------
// LayerNorm (+ optional residual, optional tf32 rounding of output)
// ---------------------------------------------------------------------------
__global__ __launch_bounds__(256) void ln_kernel(
    const float* __restrict__ in, const float* __restrict__ res,
    const float* __restrict__ w, const float* __restrict__ b,
    float* __restrict__ out, int rnd)
{
    __shared__ float red_s[8];
    __shared__ float red_q[8];
    size_t row = blockIdx.x;
    int t = threadIdx.x;

    const float4* px = (const float4*)(in + row * EDIM);
    float4 v = px[t];
    if (res != nullptr) {
        const float4* pr = (const float4*)(res + row * EDIM);
        float4 rv = pr[t];
        v.x += rv.x; v.y += rv.y; v.z += rv.z; v.w += rv.w;
    }
    float s = v.x + v.y + v.z + v.w;
    float q = v.x * v.x + v.y * v.y + v.z * v.z + v.w * v.w;
#pragma unroll
    for (int o = 16; o > 0; o >>= 1) {
        s += __shfl_xor_sync(0xffffffffu, s, o);
        q += __shfl_xor_sync(0xffffffffu, q, o);
    }
    if ((t & 31) == 0) { red_s[t >> 5] = s; red_q[t >> 5] = q; }
    __syncthreads();
    float tot = 0.f, totq = 0.f;
#pragma unroll
    for (int k = 0; k < 8; ++k) { tot += red_s[k]; totq += red_q[k]; }

    float mean = tot * (1.0f / EDIM);
    float var  = totq * (1.0f / EDIM) - mean * mean;
    float rstd = rsqrtf(var + 1e-5f);

    int c0 = t * 4;
    float4 wv = *(const float4*)(w + c0);
    float4 bv = *(const float4*)(b + c0);
    float4 o4;
    o4.x = (v.x - mean) * rstd * wv.x + bv.x;
    o4.y = (v.y - mean) * rstd * wv.y + bv.y;
    o4.z = (v.z - mean) * rstd * wv.z + bv.z;
    o4.w = (v.w - mean) * rstd * wv.w + bv.w;
    if (rnd) {
        o4.x = roundtf(o4.x); o4.y = roundtf(o4.y);
        o4.z = roundtf(o4.z); o4.w = roundtf(o4.w);
    }
    ((float4*)(out + row * EDIM))[t] = o4;
}

// ---------------------------------------------------------------------------
// Weight permute: in_w (3072x1024 row-major fp32) -> B-fragment order, tf32.
// Output: [nb 0..383][kb 0..127][lane 0..31][2]
//   val = { W[8nb+fr][8kb+fc], W[8nb+fr][8kb+fc+4] },  fr=lane>>2, fc=lane&3
// ---------------------------------------------------------------------------
#define PW_SMEM (16 * 1028 * 4)     // 65792 bytes

__global__ __launch_bounds__(256) void permute_w_kernel(
    const float* __restrict__ w, float* __restrict__ wp)
{
    extern __shared__ float s[];
    int blk = blockIdx.x;           // 0..191
    int t = threadIdx.x;
#pragma unroll
    for (int rr = 0; rr < 16; ++rr) {
        float4 v = *(const float4*)(w + (size_t)(blk * 16 + rr) * EDIM + t * 4);
        *(float4*)&s[rr * 1028 + t * 4] = v;
    }
    __syncthreads();
#pragma unroll
    for (int it = 0; it < 32; ++it) {
        int o2 = t + it * 256;              // 0..8191
        int nb_l = o2 >> 12;                // 0..1
        int kb   = (o2 >> 5) & 127;
        int lane = o2 & 31;
        int fr = lane >> 2, fc = lane & 3;
        int rl = nb_l * 8 + fr;
        float2 o;
        o.x = roundtf(s[rl * 1028 + kb * 8 + fc]);
        o.y = roundtf(s[rl * 1028 + kb * 8 + fc + 4]);
        *(float2*)(wp + (((size_t)(blk * 2 + nb_l) * 128 + kb) * 32 + lane) * 2) = o;
    }
}

// ---------------------------------------------------------------------------
// Persistent TF32 QKV GEMM (R14 verified best): BK=32, 4-stage pipeline,
// L2-resident tile order (bn = tile % 12, bm = tile / 12).
// 8 warps (2x4), warp tile 64x64, LDSM A-fragments, permuted-W LDS.64 B.
// ---------------------------------------------------------------------------
#define GS_A_BYTES 18432
#define GS_B_BYTES 32768
#define GS_STAGE   (GS_A_BYTES + GS_B_BYTES)   // 51200
#define GS_SMEM    (4 * GS_STAGE)              // 204800

__global__ __launch_bounds__(256, 1) void qkv_gemm_tf32_kernel(
    const float* __restrict__ A, const float* __restrict__ Wp,
    const float* __restrict__ bias, float* __restrict__ C)
{
    extern __shared__ char smem[];
    uint32_t sb = smem_u32(smem);
    int tid  = threadIdx.x;
    int lane = tid & 31;
    int wid  = tid >> 5;          // 0..7
    int wm   = wid >> 2;          // 0..1
    int wn   = wid & 3;           // 0..3
    int bid  = blockIdx.x;        // 0..147

    int nt_local = (NTILES - bid + NSM - 1) / NSM;
    int total_chunks = nt_local * 32;

    auto load_chunk = [&](int q) {
        int tile = bid + (q >> 5) * NSM;
        int c    = q & 31;
        int bn = tile % 12;
        int bm = tile / 12;
        uint32_t base = sb + (q & 3) * GS_STAGE;
        int kbase = c * 32;
#pragma unroll
        for (int i = 0; i < 4; ++i) {      // A: 1024 granules
            int g = tid + i * 256;
            int r = g >> 3, kk = g & 7;
            cp_async16(base + r * 144 + kk * 16,
                       A + (size_t)(bm * 128 + r) * EDIM + kbase + kk * 4);
        }
#pragma unroll
        for (int i = 0; i < 8; ++i) {      // W: 2048 granules (permuted blocks)
            int g = tid + i * 256;
            int nb = g >> 6, kb = (g >> 4) & 3, pr = g & 15;
            cp_async16(base + GS_A_BYTES + g * 16,
                       Wp + ((size_t)(bn * 32 + nb) * 128 + c * 4 + kb) * 64 + pr * 4);
        }
    };

    load_chunk(0); CP_COMMIT();
    load_chunk(1); CP_COMMIT();
    load_chunk(2); CP_COMMIT();

    float acc[4][8][4];
#pragma unroll
    for (int i = 0; i < 4; ++i)
#pragma unroll
        for (int j = 0; j < 8; ++j)
#pragma unroll
            for (int k = 0; k < 4; ++k) acc[i][j][k] = 0.f;

    uint32_t a_off = (uint32_t)((wm * 64 + (lane & 15)) * 144 + (lane >> 4) * 16);
    int qr = lane >> 2;
    int tc = (lane & 3) * 2;

    for (int q = 0; q < total_chunks; ++q) {
        asm volatile("cp.async.wait_group 2;" ::: "memory");
        __syncthreads();
        int s = q & 3;
        uint32_t sA = sb + s * GS_STAGE;
        const char* Bp = smem + s * GS_STAGE + GS_A_BYTES;

#pragma unroll
        for (int ks = 0; ks < 32; ks += 8) {
            int kb = ks >> 3;
            uint32_t fa[4][4];
            uint2 fb[8];
#pragma unroll
            for (int mt = 0; mt < 4; ++mt)
                ldsm4(fa[mt], sA + a_off + mt * (16 * 144) + ks * 4);
#pragma unroll
            for (int nt = 0; nt < 8; ++nt) {
                int nbl = wn * 8 + nt;
                fb[nt] = *(const uint2*)(Bp + (nbl * 4 + kb) * 256 + lane * 8);
            }
#pragma unroll
            for (int mt = 0; mt < 4; ++mt)
#pragma unroll
                for (int nt = 0; nt < 8; ++nt)
                    mma_tf32(acc[mt][nt], fa[mt], fb[nt].x, fb[nt].y);
        }

        if (q + 3 < total_chunks) load_chunk(q + 3);
        CP_COMMIT();

        if ((q & 31) == 31) {
            // ---- epilogue for this tile (loads for next tile in flight) ----
            int tile = bid + (q >> 5) * NSM;
            int bn = tile % 12;
            int bm = tile / 12;
            float scale = (bn < 4) ? 0.125f : 1.0f;   // q * HD^-0.5
#pragma unroll
            for (int mt = 0; mt < 4; ++mt) {
#pragma unroll
                for (int nt = 0; nt < 8; ++nt) {
                    int row = bm * 128 + wm * 64 + mt * 16 + qr;
                    int col = bn * 256 + wn * 64 + nt * 8 + tc;
                    float b0 = bias[col], b1 = bias[col + 1];
                    float2 o0 = make_float2(roundtf((acc[mt][nt][0] + b0) * scale),
                                            roundtf((acc[mt][nt][1] + b1) * scale));
                    float2 o1 = make_float2(roundtf((acc[mt][nt][2] + b0) * scale),
                                            roundtf((acc[mt][nt][3] + b1) * scale));
                    *(float2*)(C + (size_t)row * QKVDIM + col)       = o0;
                    *(float2*)(C + (size_t)(row + 8) * QKVDIM + col) = o1;
#pragma unroll
                    for (int k = 0; k < 4; ++k) acc[mt][nt][k] = 0.f;
                }
            }
        }
    }
}

// ---------------------------------------------------------------------------
// Attention: TF32 QK^T + fp16 P·V. One block (256 thr) per bh; 2 CTAs/SM.
// SMEM (floats): Qs 128x68 @0, Ks 128x68 @8704, VT fp16 64x136h @17408,
//   AVG 8x128 @21760.  Total 91136 B.
// Overlays: S fp32 (128x132) over Qs+Ks during softmax; P fp16 (128x136h,
//   34816B) over Qs after softmax; output staging (128x68 f32) over Ks.
// V loaded by LDG during QK, converted to fp16 transposed after softmax reads.
// ---------------------------------------------------------------------------
#define AT_K_F   8704
#define AT_VT_F  17408
#define AT_AVG_F 21760
#define ATTN_SMEM_BYTES ((AT_AVG_F + 8 * 128) * 4)   // 91136

__global__ void __launch_bounds__(256, 2) attn_kernel(
    const float* __restrict__ qkv, float* __restrict__ attn,
    float* __restrict__ avg_out)
{
    extern __shared__ float sm[];
    float*  AVG = sm + AT_AVG_F;
    float*  S   = sm;                       // overlays Qs+Ks after QK phase
    float*  OST = sm + AT_K_F;              // output staging (overlays Ks)
    __half* VT  = (__half*)(sm + AT_VT_F);  // V fp16, transposed [d][j]
    uint32_t sbase = smem_u32(sm);

    int bh  = blockIdx.x;
    int p   = bh >> 11;
    int rr  = bh & 2047;
    int nid = rr >> 4;
    int h   = rr & 15;
    int t   = threadIdx.x;
    int lane = t & 31;
    int wid  = t >> 5;            // 0..7
    int wm   = wid >> 2;          // 0..1
    int wn   = wid & 3;           // 0..3
    int col = h * HDIM;

    // ---- async gather of Q,K ----
#pragma unroll
    for (int it = 0; it < 8; ++it) {
        int f  = t + it * 256;          // 0..2047
        int i  = f >> 4;                // row 0..127
        int d0 = (f & 15) << 2;         // 0..60
        int rowoff = ((2 * i + p) * 128 + nid) * QKVDIM;
        cp_async16(sbase + (i * 68 + d0) * 4,
                   qkv + rowoff + col + d0);
        cp_async16(sbase + (AT_K_F + i * 68 + d0) * 4,
                   qkv + rowoff + 1024 + col + d0);
    }
    CP_COMMIT();
    asm volatile("cp.async.wait_group 0;" ::: "memory");
    __syncthreads();

    // LDSM per-lane offsets (bytes)
    uint32_t aq_off = (uint32_t)((wm * 64 + (lane & 15)) * 272 + (lane >> 4) * 16);
    uint32_t bk_row = (uint32_t)(wn * 32 + (lane & 7) + ((lane & 16) >> 1));
    uint32_t bk_off = AT_K_F * 4 + bk_row * 272 + (((lane >> 3) & 1) * 16);

    // ---- scores = Q K^T (TF32), warp tile 64x32, K=64; kept in registers ----
    float acc[4][4][4];
#pragma unroll
    for (int i = 0; i < 4; ++i)
#pragma unroll
        for (int j = 0; j < 4; ++j)
#pragma unroll
            for (int k = 0; k < 4; ++k) acc[i][j][k] = 0.f;

#pragma unroll
    for (int ks = 0; ks < 64; ks += 8) {
        uint32_t fa[4][4], fbp[2][4];
#pragma unroll
        for (int mt = 0; mt < 4; ++mt)
            ldsm4(fa[mt], sbase + aq_off + mt * (16 * 272) + ks * 4);
#pragma unroll
        for (int ntp = 0; ntp < 2; ++ntp)
            ldsm4(fbp[ntp], sbase + bk_off + ntp * (16 * 272) + ks * 4);
#pragma unroll
        for (int mt = 0; mt < 4; ++mt) {
#pragma unroll
            for (int nt = 0; nt < 4; ++nt) {
                int np = nt >> 1, hh = (nt & 1) * 2;
                mma_tf32(acc[mt][nt], fa[mt], fbp[np][hh], fbp[np][hh + 1]);
            }
        }
    }

    // ---- issue V loads (LDG) now; they land during S-store + softmax ----
    float4 vreg[8];
#pragma unroll
    for (int it = 0; it < 8; ++it) {
        int f  = t + it * 256;
        int i  = f >> 4;
        int d0 = (f & 15) << 2;
        int rowoff = ((2 * i + p) * 128 + nid) * QKVDIM;
        vreg[it] = *(const float4*)&qkv[rowoff + 2048 + col + d0];
    }

    __syncthreads();   // all warps done reading Qs/Ks before S overlays them

    {
        int qr = lane >> 2, tc = (lane & 3) * 2;
#pragma unroll
        for (int mt = 0; mt < 4; ++mt) {
#pragma unroll
            for (int nt = 0; nt < 4; ++nt) {
                int row = wm * 64 + mt * 16 + qr;
                int cc  = wn * 32 + nt * 8 + tc;
                S[row * 132 + cc]           = acc[mt][nt][0];
                S[row * 132 + cc + 1]       = acc[mt][nt][1];
                S[(row + 8) * 132 + cc]     = acc[mt][nt][2];
                S[(row + 8) * 132 + cc + 1] = acc[mt][nt][3];
            }
        }
    }
    __syncthreads();

    // ---- softmax (16 rows/warp): stage P as fp16 in regs + avg partials ----
    uint32_t pst[16][2];
    {
        float cs0 = 0.f, cs1 = 0.f, cs2 = 0.f, cs3 = 0.f;
#pragma unroll
        for (int r8 = 0; r8 < 16; ++r8) {
            int row = wid * 16 + r8;
            float4 v = *(float4*)&S[row * 132 + lane * 4];
            float mx = fmaxf(fmaxf(v.x, v.y), fmaxf(v.z, v.w));
#pragma unroll
            for (int o = 16; o > 0; o >>= 1)
                mx = fmaxf(mx, __shfl_xor_sync(0xffffffffu, mx, o));
            v.x = __expf(v.x - mx); v.y = __expf(v.y - mx);
            v.z = __expf(v.z - mx); v.w = __expf(v.w - mx);
            float sum = v.x + v.y + v.z + v.w;
#pragma unroll
            for (int o = 16; o > 0; o >>= 1)
                sum += __shfl_xor_sync(0xffffffffu, sum, o);
            float inv = 1.0f / sum;
            v.x *= inv; v.y *= inv; v.z *= inv; v.w *= inv;
            cs0 += v.x; cs1 += v.y; cs2 += v.z; cs3 += v.w;
            __half2 p01 = __floats2half2_rn(v.x, v.y);
            __half2 p23 = __floats2half2_rn(v.z, v.w);
            pst[r8][0] = *(uint32_t*)&p01;
            pst[r8][1] = *(uint32_t*)&p23;
        }
        *(float4*)&AVG[wid * 128 + lane * 4] = make_float4(cs0, cs1, cs2, cs3);
    }

    // ---- V: fp32 regs -> fp16 transposed smem (VT[d][j], stride 136 halfs) --
#pragma unroll
    for (int it = 0; it < 8; ++it) {
        int f  = t + it * 256;
        int i  = f >> 4;
        int d0 = (f & 15) << 2;
        VT[(d0 + 0) * 136 + i] = __float2half(vreg[it].x);
        VT[(d0 + 1) * 136 + i] = __float2half(vreg[it].y);
        VT[(d0 + 2) * 136 + i] = __float2half(vreg[it].z);
        VT[(d0 + 3) * 136 + i] = __float2half(vreg[it].w);
    }
    __syncthreads();   // S reads done everywhere; VT/AVG visible

    // ---- write P fp16 (overlays Q region) + avg final ----
#pragma unroll
    for (int r8 = 0; r8 < 16; ++r8) {
        int row = wid * 16 + r8;
        *(uint2*)((char*)sm + row * 272 + lane * 8) =
            make_uint2(pst[r8][0], pst[r8][1]);
    }
    if (t < 128) {
        float s = 0.f;
#pragma unroll
        for (int w = 0; w < 8; ++w) s += AVG[w * 128 + t];
        avg_out[bh * 128 + t] = s * 0.0625f;
    }
    __syncthreads();   // P visible

    // ---- A·V (fp16 m16n8k16): A = P via LDSM, B = VT via LDS.32 pairs ----
    float av[4][2][4];
    {
        uint32_t pa_off = (uint32_t)((wm * 64 + (lane & 15)) * 272 + (lane >> 4) * 16);
        const __half* vb = VT + (wn * 16 + (lane >> 2)) * 136 + 2 * (lane & 3);
#pragma unroll
        for (int i = 0; i < 4; ++i)
#pragma unroll
            for (int j = 0; j < 2; ++j)
#pragma unroll
                for (int k = 0; k < 4; ++k) av[i][j][k] = 0.f;

#pragma unroll
        for (int ks = 0; ks < 128; ks += 16) {
            uint32_t fa[4][4];
#pragma unroll
            for (int mt = 0; mt < 4; ++mt)
                ldsm4(fa[mt], sbase + pa_off + mt * (16 * 272) + ks * 2);
            uint32_t b00 = *(const uint32_t*)(vb + ks);
            uint32_t b01 = *(const uint32_t*)(vb + ks + 8);
            uint32_t b10 = *(const uint32_t*)(vb + 8 * 136 + ks);
            uint32_t b11 = *(const uint32_t*)(vb + 8 * 136 + ks + 8);
#pragma unroll
            for (int mt = 0; mt < 4; ++mt) {
                mma_f16(av[mt][0], fa[mt], b00, b01);
                mma_f16(av[mt][1], fa[mt], b10, b11);
            }
        }
    }
    __syncthreads();   // everyone done reading P before OST overlays K region

    // ---- stage output in smem (stride 68, over K region), coalesced stores --
    {
        int qr = lane >> 2, tc = (lane & 3) * 2;
#pragma unroll
        for (int mt = 0; mt < 4; ++mt) {
#pragma unroll
            for (int nt = 0; nt < 2; ++nt) {
                int row = wm * 64 + mt * 16 + qr;
                int cc  = wn * 16 + nt * 8 + tc;
                *(float2*)&OST[row * 68 + cc] =
                    make_float2(av[mt][nt][0], av[mt][nt][1]);
                *(float2*)&OST[(row + 8) * 68 + cc] =
                    make_float2(av[mt][nt][2], av[mt][nt][3]);
            }
        }
    }
    __syncthreads();
#pragma unroll
    for (int it = 0; it < 8; ++it) {
        int f  = t + it * 256;
        int row = f >> 4;
        int c4  = (f & 15) << 2;
        float4 v = *(float4*)&OST[row * 68 + c4];
        int orow = (2 * row + p) * 128 + nid;
        *(float4*)&attn[(size_t)orow * EDIM + col + c4] = v;
    }
}

// ---------------------------------------------------------------------------
// Launch
// ---------------------------------------------------------------------------
extern "C" void kernel_launch(void* const* d_in, const int* in_sizes, int n_in,
                              void* d_out, int out_size)
{
    const float* x    = (const float*)d_in[0];
    const float* ln1w = (const float*)d_in[1];
    const float* ln1b = (const float*)d_in[2];
    const float* inw  = (const float*)d_in[3];
    const float* inb  = (const float*)d_in[4];
    const float* ln2w = (const float*)d_in[5];
    const float* ln2b = (const float*)d_in[6];
    float* out = (float*)d_out;

    float *xn, *qkv, *attn, *wtf;
    cudaGetSymbolAddress((void**)&xn,   g_xn);
    cudaGetSymbolAddress((void**)&qkv,  g_qkv);
    cudaGetSymbolAddress((void**)&attn, g_attn);
    cudaGetSymbolAddress((void**)&wtf,  g_wtf);

    cudaFuncSetAttribute(attn_kernel,
                         cudaFuncAttributeMaxDynamicSharedMemorySize,
                         ATTN_SMEM_BYTES);
    cudaFuncSetAttribute(qkv_gemm_tf32_kernel,
                         cudaFuncAttributeMaxDynamicSharedMemorySize,
                         GS_SMEM);
    cudaFuncSetAttribute(permute_w_kernel,
                         cudaFuncAttributeMaxDynamicSharedMemorySize,
                         PW_SMEM);

    // 1) xn = LN1(x), tf32-rounded (also the residual for LN2)
    ln_kernel<<<NROWS, 256>>>(x, nullptr, ln1w, ln1b, xn, 1);
    // 2) permute + round weights into B-fragment layout
    permute_w_kernel<<<192, 256, PW_SMEM>>>(inw, wtf);
    // 3) persistent TF32 QKV GEMM (R14 verified best)
    qkv_gemm_tf32_kernel<<<NSM, 256, GS_SMEM>>>(xn, wtf, inb, qkv);
    // 4) attention: TF32 QK^T + fp16 P·V, fused avg_w
    attn_kernel<<<NBH, 256, ATTN_SMEM_BYTES>>>(qkv, attn, out + OUT_ELEMS);
    // 5) out = LN2(xn + attn)
    ln_kernel<<<NROWS, 256>>>(xn, attn, ln2w, ln2b, out, 0);
}

// round 16
// speedup vs baseline: 1.0138x; 1.0138x over previous
#include <cuda_runtime.h>
#include <cstdint>

// ---------------------------------------------------------------------------
// Problem constants
// ---------------------------------------------------------------------------
#define EDIM   1024
#define NAQ    128
#define BSZ    256
#define NROWS  (BSZ * NAQ)          // 32768
#define QKVDIM 3072
#define HEADS  16
#define HDIM   64
#define NBH    (BSZ * HEADS)        // 4096 attention batches
#define OUT_ELEMS (NROWS * EDIM)
#define NTILES 3072                 // 256 bm x 12 bn
#define NSM    148

// ---------------------------------------------------------------------------
// Scratch (device globals: allocation-free)
// ---------------------------------------------------------------------------
__device__ float g_xn  [(size_t)NROWS * EDIM];       // ln1(x), tf32-rounded
__device__ float g_qkv [(size_t)NROWS * QKVDIM];     // qkv (q scaled), tf32-rounded
__device__ float g_attn[(size_t)NROWS * EDIM];       // attention output
__device__ float g_wtf [(size_t)QKVDIM * EDIM];      // in_w, fragment-permuted tf32

// ---------------------------------------------------------------------------
// Helpers (portable subset: harness lowers through compute_103)
// ---------------------------------------------------------------------------
__device__ __forceinline__ uint32_t smem_u32(const void* p) {
    uint32_t a;
    asm("{ .reg .u64 t; cvta.to.shared.u64 t, %1; cvt.u32.u64 %0, t; }"
        : "=r"(a) : "l"(p));
    return a;
}
__device__ __forceinline__ void cp_async16(uint32_t dst, const void* src) {
    asm volatile("cp.async.cg.shared.global [%0], [%1], 16;"
                 :: "r"(dst), "l"(src) : "memory");
}
#define CP_COMMIT() asm volatile("cp.async.commit_group;" ::: "memory")

__device__ __forceinline__ uint32_t f2tf(float f) {
    uint32_t r;
    asm("cvt.rna.tf32.f32 %0, %1;" : "=r"(r) : "f"(f));
    return r;
}
__device__ __forceinline__ float roundtf(float f) {
    return __uint_as_float(f2tf(f));
}
__device__ __forceinline__ void mma_tf32(float* c, const uint32_t* a,
                                         uint32_t b0, uint32_t b1) {
    asm volatile(
        "mma.sync.aligned.m16n8k8.row.col.f32.tf32.tf32.f32 "
        "{%0,%1,%2,%3}, {%4,%5,%6,%7}, {%8,%9}, {%0,%1,%2,%3};"
        : "+f"(c[0]), "+f"(c[1]), "+f"(c[2]), "+f"(c[3])
        : "r"(a[0]), "r"(a[1]), "r"(a[2]), "r"(a[3]), "r"(b0), "r"(b1));
}
__device__ __forceinline__ void ldsm4(uint32_t* r, uint32_t addr) {
    asm volatile("ldmatrix.sync.aligned.m8n8.x4.shared.b16 {%0,%1,%2,%3}, [%4];"
                 : "=r"(r[0]), "=r"(r[1]), "=r"(r[2]), "=r"(r[3]) : "r"(addr));
}

// ---------------------------------------------------------------------------
// LayerNorm, warp-per-row: 8 warps/block, one 1024-float row per warp.
// No smem, no __syncthreads — pure register + shfl reduction.
// Optional residual add and tf32 rounding of the output.
// ---------------------------------------------------------------------------
__global__ __launch_bounds__(256) void ln_kernel(
    const float* __restrict__ in, const float* __restrict__ res,
    const float* __restrict__ w, const float* __restrict__ b,
    float* __restrict__ out, int rnd)
{
    int wid  = threadIdx.x >> 5;
    int lane = threadIdx.x & 31;
    size_t row = (size_t)blockIdx.x * 8 + wid;

    const float* px = in + row * EDIM;
    float4 v[8];
#pragma unroll
    for (int i = 0; i < 8; ++i)
        v[i] = *(const float4*)(px + i * 128 + lane * 4);
    if (res != nullptr) {
        const float* pr = res + row * EDIM;
#pragma unroll
        for (int i = 0; i < 8; ++i) {
            float4 rv = *(const float4*)(pr + i * 128 + lane * 4);
            v[i].x += rv.x; v[i].y += rv.y; v[i].z += rv.z; v[i].w += rv.w;
        }
    }

    float s = 0.f, q = 0.f;
#pragma unroll
    for (int i = 0; i < 8; ++i) {
        s += v[i].x + v[i].y + v[i].z + v[i].w;
        q += v[i].x * v[i].x + v[i].y * v[i].y
           + v[i].z * v[i].z + v[i].w * v[i].w;
    }
#pragma unroll
    for (int o = 16; o > 0; o >>= 1) {
        s += __shfl_xor_sync(0xffffffffu, s, o);
        q += __shfl_xor_sync(0xffffffffu, q, o);
    }

    float mean = s * (1.0f / EDIM);
    float var  = q * (1.0f / EDIM) - mean * mean;
    float rstd = rsqrtf(var + 1e-5f);

    float* po = out + row * EDIM;
#pragma unroll
    for (int i = 0; i < 8; ++i) {
        int c0 = i * 128 + lane * 4;
        float4 wv = *(const float4*)(w + c0);
        float4 bv = *(const float4*)(b + c0);
        float4 o4;
        o4.x = (v[i].x - mean) * rstd * wv.x + bv.x;
        o4.y = (v[i].y - mean) * rstd * wv.y + bv.y;
        o4.z = (v[i].z - mean) * rstd * wv.z + bv.z;
        o4.w = (v[i].w - mean) * rstd * wv.w + bv.w;
        if (rnd) {
            o4.x = roundtf(o4.x); o4.y = roundtf(o4.y);
            o4.z = roundtf(o4.z); o4.w = roundtf(o4.w);
        }
        *(float4*)(po + c0) = o4;
    }
}

// ---------------------------------------------------------------------------
// Weight permute: in_w (3072x1024 row-major fp32) -> B-fragment order, tf32.
// Output: [nb 0..383][kb 0..127][lane 0..31][2]
//   val = { W[8nb+fr][8kb+fc], W[8nb+fr][8kb+fc+4] },  fr=lane>>2, fc=lane&3
// ---------------------------------------------------------------------------
#define PW_SMEM (16 * 1028 * 4)     // 65792 bytes

__global__ __launch_bounds__(256) void permute_w_kernel(
    const float* __restrict__ w, float* __restrict__ wp)
{
    extern __shared__ float s[];
    int blk = blockIdx.x;           // 0..191
    int t = threadIdx.x;
#pragma unroll
    for (int rr = 0; rr < 16; ++rr) {
        float4 v = *(const float4*)(w + (size_t)(blk * 16 + rr) * EDIM + t * 4);
        *(float4*)&s[rr * 1028 + t * 4] = v;
    }
    __syncthreads();
#pragma unroll
    for (int it = 0; it < 32; ++it) {
        int o2 = t + it * 256;              // 0..8191
        int nb_l = o2 >> 12;                // 0..1
        int kb   = (o2 >> 5) & 127;
        int lane = o2 & 31;
        int fr = lane >> 2, fc = lane & 3;
        int rl = nb_l * 8 + fr;
        float2 o;
        o.x = roundtf(s[rl * 1028 + kb * 8 + fc]);
        o.y = roundtf(s[rl * 1028 + kb * 8 + fc + 4]);
        *(float2*)(wp + (((size_t)(blk * 2 + nb_l) * 128 + kb) * 32 + lane) * 2) = o;
    }
}

// ---------------------------------------------------------------------------
// Persistent TF32 QKV GEMM (R14 verified best): BK=32, 4-stage pipeline,
// L2-resident tile order (bn = tile % 12, bm = tile / 12).
// 8 warps (2x4), warp tile 64x64, LDSM A-fragments, permuted-W LDS.64 B.
// ---------------------------------------------------------------------------
#define GS_A_BYTES 18432
#define GS_B_BYTES 32768
#define GS_STAGE   (GS_A_BYTES + GS_B_BYTES)   // 51200
#define GS_SMEM    (4 * GS_STAGE)              // 204800

__global__ __launch_bounds__(256, 1) void qkv_gemm_tf32_kernel(
    const float* __restrict__ A, const float* __restrict__ Wp,
    const float* __restrict__ bias, float* __restrict__ C)
{
    extern __shared__ char smem[];
    uint32_t sb = smem_u32(smem);
    int tid  = threadIdx.x;
    int lane = tid & 31;
    int wid  = tid >> 5;          // 0..7
    int wm   = wid >> 2;          // 0..1
    int wn   = wid & 3;           // 0..3
    int bid  = blockIdx.x;        // 0..147

    int nt_local = (NTILES - bid + NSM - 1) / NSM;
    int total_chunks = nt_local * 32;

    auto load_chunk = [&](int q) {
        int tile = bid + (q >> 5) * NSM;
        int c    = q & 31;
        int bn = tile % 12;
        int bm = tile / 12;
        uint32_t base = sb + (q & 3) * GS_STAGE;
        int kbase = c * 32;
#pragma unroll
        for (int i = 0; i < 4; ++i) {      // A: 1024 granules
            int g = tid + i * 256;
            int r = g >> 3, kk = g & 7;
            cp_async16(base + r * 144 + kk * 16,
                       A + (size_t)(bm * 128 + r) * EDIM + kbase + kk * 4);
        }
#pragma unroll
        for (int i = 0; i < 8; ++i) {      // W: 2048 granules (permuted blocks)
            int g = tid + i * 256;
            int nb = g >> 6, kb = (g >> 4) & 3, pr = g & 15;
            cp_async16(base + GS_A_BYTES + g * 16,
                       Wp + ((size_t)(bn * 32 + nb) * 128 + c * 4 + kb) * 64 + pr * 4);
        }
    };

    load_chunk(0); CP_COMMIT();
    load_chunk(1); CP_COMMIT();
    load_chunk(2); CP_COMMIT();

    float acc[4][8][4];
#pragma unroll
    for (int i = 0; i < 4; ++i)
#pragma unroll
        for (int j = 0; j < 8; ++j)
#pragma unroll
            for (int k = 0; k < 4; ++k) acc[i][j][k] = 0.f;

    uint32_t a_off = (uint32_t)((wm * 64 + (lane & 15)) * 144 + (lane >> 4) * 16);
    int qr = lane >> 2;
    int tc = (lane & 3) * 2;

    for (int q = 0; q < total_chunks; ++q) {
        asm volatile("cp.async.wait_group 2;" ::: "memory");
        __syncthreads();
        int s = q & 3;
        uint32_t sA = sb + s * GS_STAGE;
        const char* Bp = smem + s * GS_STAGE + GS_A_BYTES;

#pragma unroll
        for (int ks = 0; ks < 32; ks += 8) {
            int kb = ks >> 3;
            uint32_t fa[4][4];
            uint2 fb[8];
#pragma unroll
            for (int mt = 0; mt < 4; ++mt)
                ldsm4(fa[mt], sA + a_off + mt * (16 * 144) + ks * 4);
#pragma unroll
            for (int nt = 0; nt < 8; ++nt) {
                int nbl = wn * 8 + nt;
                fb[nt] = *(const uint2*)(Bp + (nbl * 4 + kb) * 256 + lane * 8);
            }
#pragma unroll
            for (int mt = 0; mt < 4; ++mt)
#pragma unroll
                for (int nt = 0; nt < 8; ++nt)
                    mma_tf32(acc[mt][nt], fa[mt], fb[nt].x, fb[nt].y);
        }

        if (q + 3 < total_chunks) load_chunk(q + 3);
        CP_COMMIT();

        if ((q & 31) == 31) {
            // ---- epilogue for this tile (loads for next tile in flight) ----
            int tile = bid + (q >> 5) * NSM;
            int bn = tile % 12;
            int bm = tile / 12;
            float scale = (bn < 4) ? 0.125f : 1.0f;   // q * HD^-0.5
#pragma unroll
            for (int mt = 0; mt < 4; ++mt) {
#pragma unroll
                for (int nt = 0; nt < 8; ++nt) {
                    int row = bm * 128 + wm * 64 + mt * 16 + qr;
                    int col = bn * 256 + wn * 64 + nt * 8 + tc;
                    float b0 = bias[col], b1 = bias[col + 1];
                    float2 o0 = make_float2(roundtf((acc[mt][nt][0] + b0) * scale),
                                            roundtf((acc[mt][nt][1] + b1) * scale));
                    float2 o1 = make_float2(roundtf((acc[mt][nt][2] + b0) * scale),
                                            roundtf((acc[mt][nt][3] + b1) * scale));
                    *(float2*)(C + (size_t)row * QKVDIM + col)       = o0;
                    *(float2*)(C + (size_t)(row + 8) * QKVDIM + col) = o1;
#pragma unroll
                    for (int k = 0; k < 4; ++k) acc[mt][nt][k] = 0.f;
                }
            }
        }
    }
}

// ---------------------------------------------------------------------------
// Attention via TF32 mma.sync + LDSM (R12/R14 winner): one block per bh;
// 2 CTAs/SM. SMEM (floats): Qs 128x68 @0, Ks 128x68 @8704, Vs 128x72 @17408,
// AVG 8x128 @26624. S (128x132) overlays Qs+Ks after QK^T.
// avg_w fused into softmax; V cp.async group overlaps QK + softmax.
// ---------------------------------------------------------------------------
#define AT_K_F   8704
#define AT_V_F   17408
#define AT_AVG_F 26624
#define ATTN_SMEM_BYTES ((AT_AVG_F + 8 * 128) * 4)   // 110592

__global__ void __launch_bounds__(256, 2) attn_kernel(
    const float* __restrict__ qkv, float* __restrict__ attn,
    float* __restrict__ avg_out)
{
    extern __shared__ float sm[];
    float* Vs  = sm + AT_V_F;
    float* AVG = sm + AT_AVG_F;
    float* S   = sm;                // overlays Qs+Ks after QK phase
    uint32_t sbase = smem_u32(sm);

    int bh  = blockIdx.x;
    int p   = bh >> 11;
    int rr  = bh & 2047;
    int nid = rr >> 4;
    int h   = rr & 15;
    int t   = threadIdx.x;
    int lane = t & 31;
    int wid  = t >> 5;            // 0..7
    int wm   = wid >> 2;          // 0..1
    int wn   = wid & 3;           // 0..3
    int col = h * HDIM;

    // ---- async gather of Q,K (group 1) and V (group 0, overlapped) ----
#pragma unroll
    for (int it = 0; it < 8; ++it) {
        int f  = t + it * 256;          // 0..2047
        int i  = f >> 4;                // row 0..127
        int d0 = (f & 15) << 2;         // 0..60
        int rowoff = ((2 * i + p) * 128 + nid) * QKVDIM;
        cp_async16(sbase + (i * 68 + d0) * 4,
                   qkv + rowoff + col + d0);
        cp_async16(sbase + (AT_K_F + i * 68 + d0) * 4,
                   qkv + rowoff + 1024 + col + d0);
    }
    CP_COMMIT();
#pragma unroll
    for (int it = 0; it < 8; ++it) {
        int f  = t + it * 256;
        int i  = f >> 4;
        int d0 = (f & 15) << 2;
        int rowoff = ((2 * i + p) * 128 + nid) * QKVDIM;
        cp_async16(sbase + (AT_V_F + i * 72 + d0) * 4,
                   qkv + rowoff + 2048 + col + d0);
    }
    CP_COMMIT();
    asm volatile("cp.async.wait_group 1;" ::: "memory");  // Q,K ready
    __syncthreads();

    // LDSM per-lane offsets (bytes)
    uint32_t aq_off = (uint32_t)((wm * 64 + (lane & 15)) * 272 + (lane >> 4) * 16);
    uint32_t bk_row = (uint32_t)(wn * 32 + (lane & 7) + ((lane & 16) >> 1));
    uint32_t bk_off = AT_K_F * 4 + bk_row * 272 + (((lane >> 3) & 1) * 16);

    // ---- scores = Q K^T (TF32), warp tile 64x32, K=64; kept in registers ----
    float acc[4][4][4];
#pragma unroll
    for (int i = 0; i < 4; ++i)
#pragma unroll
        for (int j = 0; j < 4; ++j)
#pragma unroll
            for (int k = 0; k < 4; ++k) acc[i][j][k] = 0.f;

#pragma unroll
    for (int ks = 0; ks < 64; ks += 8) {
        uint32_t fa[4][4], fbp[2][4];
#pragma unroll
        for (int mt = 0; mt < 4; ++mt)
            ldsm4(fa[mt], sbase + aq_off + mt * (16 * 272) + ks * 4);
#pragma unroll
        for (int ntp = 0; ntp < 2; ++ntp)
            ldsm4(fbp[ntp], sbase + bk_off + ntp * (16 * 272) + ks * 4);
#pragma unroll
        for (int mt = 0; mt < 4; ++mt) {
#pragma unroll
            for (int nt = 0; nt < 4; ++nt) {
                int np = nt >> 1, hh = (nt & 1) * 2;
                mma_tf32(acc[mt][nt], fa[mt], fbp[np][hh], fbp[np][hh + 1]);
            }
        }
    }
    __syncthreads();   // all warps done reading Qs/Ks before S overlays them

    {
        int qr = lane >> 2, tc = (lane & 3) * 2;
#pragma unroll
        for (int mt = 0; mt < 4; ++mt) {
#pragma unroll
            for (int nt = 0; nt < 4; ++nt) {
                int row = wm * 64 + mt * 16 + qr;
                int cc  = wn * 32 + nt * 8 + tc;
                S[row * 132 + cc]           = acc[mt][nt][0];
                S[row * 132 + cc + 1]       = acc[mt][nt][1];
                S[(row + 8) * 132 + cc]     = acc[mt][nt][2];
                S[(row + 8) * 132 + cc + 1] = acc[mt][nt][3];
            }
        }
    }
    __syncthreads();

    // ---- softmax (16 rows/warp, lane-parallel) + fused avg_w partials ----
    {
        float cs0 = 0.f, cs1 = 0.f, cs2 = 0.f, cs3 = 0.f;
#pragma unroll
        for (int r8 = 0; r8 < 16; ++r8) {
            int row = wid * 16 + r8;
            float4 v = *(float4*)&S[row * 132 + lane * 4];
            float mx = fmaxf(fmaxf(v.x, v.y), fmaxf(v.z, v.w));
#pragma unroll
            for (int o = 16; o > 0; o >>= 1)
                mx = fmaxf(mx, __shfl_xor_sync(0xffffffffu, mx, o));
            v.x = __expf(v.x - mx); v.y = __expf(v.y - mx);
            v.z = __expf(v.z - mx); v.w = __expf(v.w - mx);
            float sum = v.x + v.y + v.z + v.w;
#pragma unroll
            for (int o = 16; o > 0; o >>= 1)
                sum += __shfl_xor_sync(0xffffffffu, sum, o);
            float inv = 1.0f / sum;
            v.x = roundtf(v.x * inv); v.y = roundtf(v.y * inv);
            v.z = roundtf(v.z * inv); v.w = roundtf(v.w * inv);
            cs0 += v.x; cs1 += v.y; cs2 += v.z; cs3 += v.w;
            *(float4*)&S[row * 132 + lane * 4] = v;
        }
        *(float4*)&AVG[wid * 128 + lane * 4] = make_float4(cs0, cs1, cs2, cs3);
    }
    asm volatile("cp.async.wait_group 0;" ::: "memory");  // V ready
    __syncthreads();

    // ---- avg_w final reduce across 8 warps ----
    if (t < 128) {
        float s = 0.f;
#pragma unroll
        for (int w = 0; w < 8; ++w) s += AVG[w * 128 + t];
        avg_out[bh * 128 + t] = s * 0.0625f;
    }

    // ---- A·V (TF32): A = S via LDSM, warp tile 64x16, K=128 ----
    float av[4][2][4];
    {
        int fr = lane >> 2;
        int fc = lane & 3;
        uint32_t as_off = (uint32_t)((wm * 64 + (lane & 15)) * 528 + (lane >> 4) * 16);
#pragma unroll
        for (int i = 0; i < 4; ++i)
#pragma unroll
            for (int j = 0; j < 2; ++j)
#pragma unroll
                for (int k = 0; k < 4; ++k) av[i][j][k] = 0.f;

#pragma unroll
        for (int ks = 0; ks < 128; ks += 8) {
            uint32_t fa[4][4], fb[2][2];
#pragma unroll
            for (int mt = 0; mt < 4; ++mt)
                ldsm4(fa[mt], sbase + as_off + mt * (16 * 528) + ks * 4);
#pragma unroll
            for (int nt = 0; nt < 2; ++nt) {
                int nb = wn * 16 + nt * 8 + fr;
                fb[nt][0] = __float_as_uint(Vs[(ks + fc) * 72 + nb]);
                fb[nt][1] = __float_as_uint(Vs[(ks + fc + 4) * 72 + nb]);
            }
#pragma unroll
            for (int mt = 0; mt < 4; ++mt)
#pragma unroll
                for (int nt = 0; nt < 2; ++nt)
                    mma_tf32(av[mt][nt], fa[mt], fb[nt][0], fb[nt][1]);
        }
    }
    __syncthreads();   // everyone done reading S before OUT overlays it

    // ---- stage output in smem (stride 68), then coalesced global stores ----
    {
        int qr = lane >> 2, tc = (lane & 3) * 2;
#pragma unroll
        for (int mt = 0; mt < 4; ++mt) {
#pragma unroll
            for (int nt = 0; nt < 2; ++nt) {
                int row = wm * 64 + mt * 16 + qr;
                int cc  = wn * 16 + nt * 8 + tc;
                *(float2*)&S[row * 68 + cc] =
                    make_float2(av[mt][nt][0], av[mt][nt][1]);
                *(float2*)&S[(row + 8) * 68 + cc] =
                    make_float2(av[mt][nt][2], av[mt][nt][3]);
            }
        }
    }
    __syncthreads();
#pragma unroll
    for (int it = 0; it < 8; ++it) {
        int f  = t + it * 256;
        int row = f >> 4;
        int c4  = (f & 15) << 2;
        float4 v = *(float4*)&S[row * 68 + c4];
        int orow = (2 * row + p) * 128 + nid;
        *(float4*)&attn[(size_t)orow * EDIM + col + c4] = v;
    }
}

// ---------------------------------------------------------------------------
// Launch
// ---------------------------------------------------------------------------
extern "C" void kernel_launch(void* const* d_in, const int* in_sizes, int n_in,
                              void* d_out, int out_size)
{
    const float* x    = (const float*)d_in[0];
    const float* ln1w = (const float*)d_in[1];
    const float* ln1b = (const float*)d_in[2];
    const float* inw  = (const float*)d_in[3];
    const float* inb  = (const float*)d_in[4];
    const float* ln2w = (const float*)d_in[5];
    const float* ln2b = (const float*)d_in[6];
    float* out = (float*)d_out;

    float *xn, *qkv, *attn, *wtf;
    cudaGetSymbolAddress((void**)&xn,   g_xn);
    cudaGetSymbolAddress((void**)&qkv,  g_qkv);
    cudaGetSymbolAddress((void**)&attn, g_attn);
    cudaGetSymbolAddress((void**)&wtf,  g_wtf);

    cudaFuncSetAttribute(attn_kernel,
                         cudaFuncAttributeMaxDynamicSharedMemorySize,
                         ATTN_SMEM_BYTES);
    cudaFuncSetAttribute(qkv_gemm_tf32_kernel,
                         cudaFuncAttributeMaxDynamicSharedMemorySize,
                         GS_SMEM);
    cudaFuncSetAttribute(permute_w_kernel,
                         cudaFuncAttributeMaxDynamicSharedMemorySize,
                         PW_SMEM);

    // 1) xn = LN1(x), tf32-rounded (warp-per-row, no barriers)
    ln_kernel<<<NROWS / 8, 256>>>(x, nullptr, ln1w, ln1b, xn, 1);
    // 2) permute + round weights into B-fragment layout
    permute_w_kernel<<<192, 256, PW_SMEM>>>(inw, wtf);
    // 3) persistent TF32 QKV GEMM (R14 verified best)
    qkv_gemm_tf32_kernel<<<NSM, 256, GS_SMEM>>>(xn, wtf, inb, qkv);
    // 4) TF32 attention + avg_w (R14 winner)
    attn_kernel<<<NBH, 256, ATTN_SMEM_BYTES>>>(qkv, attn, out + OUT_ELEMS);
    // 5) out = LN2(xn + attn)
    ln_kernel<<<NROWS / 8, 256>>>(xn, attn, ln2w, ln2b, out, 0);
}